// round 1
// baseline (speedup 1.0000x reference)
#include <cuda_runtime.h>

typedef unsigned long long ull;

#define NTOK 16384
#define DDIM 2048
#define NEXP 64
#define TM   128
#define KB   32
#define KITER (DDIM / KB)   // 64
#define WS_STRIDE 68        // padded W tile stride (floats), 16B-aligned rows, low STS conflicts
#define LS_STRIDE 65        // logits smem stride

__device__ __forceinline__ ull pack2(float lo, float hi) {
    ull r;
    asm("mov.b64 %0, {%1,%2};" : "=l"(r) : "f"(lo), "f"(hi));
    return r;
}
__device__ __forceinline__ void unpack2(ull v, float& lo, float& hi) {
    asm("mov.b64 {%0,%1}, %2;" : "=f"(lo), "=f"(hi) : "l"(v));
}
__device__ __forceinline__ ull ffma2(ull a, ull b, ull c) {
    ull d;
    asm("fma.rn.f32x2 %0, %1, %2, %3;" : "=l"(d) : "l"(a), "l"(b), "l"(c));
    return d;
}

__global__ __launch_bounds__(256, 1) void router_fused_kernel(
    const float* __restrict__ x,
    const float* __restrict__ W,
    const float* __restrict__ sc,
    const float* __restrict__ noise,
    const int*   __restrict__ sidx_p,
    float*       __restrict__ out,
    int do_probs, int do_idx)
{
    // Union: GEMM staging (xs: 32x128 + ws: 32x68 = 25088 B) vs logits (128x65 = 33280 B)
    __shared__ float smem[TM * LS_STRIDE];
    float* xs = smem;               // [k][tok], KB*TM floats
    float* ws = smem + KB * TM;     // [k][e],  KB*WS_STRIDE floats

    const int t   = threadIdx.x;
    const int blk = blockIdx.x;
    const int tg  = t & 31;   // token group: tokens tg*4 .. tg*4+3
    const int eg  = t >> 5;   // expert group (warp id): experts eg*8 .. eg*8+7

    const float* xg = x + (long)blk * TM * DDIM;

    // x loader: thread covers row = t>>1 (0..127), 16 consecutive k at half*16
    const int xrow  = t >> 1;
    const int xhalf = t & 1;
    // W loader: two (e, kq) assignments per thread
    const int we0 = t >> 3,         wk0 = t & 7;
    const int we1 = (t + 256) >> 3, wk1 = (t + 256) & 7;

    ull acc[4][4];
#pragma unroll
    for (int i = 0; i < 4; ++i)
#pragma unroll
        for (int j = 0; j < 4; ++j) acc[i][j] = 0ULL;  // {+0.f,+0.f}

    float4 xr[4], wr[2];
    // prefetch k0 = 0
    {
        const float* xb = xg + xrow * DDIM + xhalf * 16;
#pragma unroll
        for (int q = 0; q < 4; ++q) xr[q] = *(const float4*)(xb + q * 4);
        wr[0] = *(const float4*)(W + we0 * DDIM + wk0 * 4);
        wr[1] = *(const float4*)(W + we1 * DDIM + wk1 * 4);
    }

    for (int it = 0; it < KITER; ++it) {
        __syncthreads();  // prior compute done before smem overwrite
        // stage x tile transposed: xs[k][tok]
#pragma unroll
        for (int q = 0; q < 4; ++q) {
            int kl = xhalf * 16 + q * 4;
            xs[(kl + 0) * TM + xrow] = xr[q].x;
            xs[(kl + 1) * TM + xrow] = xr[q].y;
            xs[(kl + 2) * TM + xrow] = xr[q].z;
            xs[(kl + 3) * TM + xrow] = xr[q].w;
        }
        // stage W tile transposed: ws[k][e]
        ws[(wk0 * 4 + 0) * WS_STRIDE + we0] = wr[0].x;
        ws[(wk0 * 4 + 1) * WS_STRIDE + we0] = wr[0].y;
        ws[(wk0 * 4 + 2) * WS_STRIDE + we0] = wr[0].z;
        ws[(wk0 * 4 + 3) * WS_STRIDE + we0] = wr[0].w;
        ws[(wk1 * 4 + 0) * WS_STRIDE + we1] = wr[1].x;
        ws[(wk1 * 4 + 1) * WS_STRIDE + we1] = wr[1].y;
        ws[(wk1 * 4 + 2) * WS_STRIDE + we1] = wr[1].z;
        ws[(wk1 * 4 + 3) * WS_STRIDE + we1] = wr[1].w;
        __syncthreads();

        // prefetch next tile into registers (overlaps with compute below)
        if (it + 1 < KITER) {
            const int k0 = (it + 1) * KB;
            const float* xb = xg + xrow * DDIM + k0 + xhalf * 16;
#pragma unroll
            for (int q = 0; q < 4; ++q) xr[q] = *(const float4*)(xb + q * 4);
            wr[0] = *(const float4*)(W + we0 * DDIM + k0 + wk0 * 4);
            wr[1] = *(const float4*)(W + we1 * DDIM + k0 + wk1 * 4);
        }

        const float4* xs4 = (const float4*)xs;   // row stride TM/4 = 32
        const float4* ws4 = (const float4*)ws;   // row stride WS_STRIDE/4 = 17
#pragma unroll 8
        for (int kk = 0; kk < KB; ++kk) {
            float4 xv = xs4[kk * (TM / 4) + tg];
            float4 wa = ws4[kk * (WS_STRIDE / 4) + eg * 2];
            float4 wb = ws4[kk * (WS_STRIDE / 4) + eg * 2 + 1];
            ull w0 = pack2(wa.x, wa.y);
            ull w1 = pack2(wa.z, wa.w);
            ull w2 = pack2(wb.x, wb.y);
            ull w3 = pack2(wb.z, wb.w);
            float xv_[4] = {xv.x, xv.y, xv.z, xv.w};
#pragma unroll
            for (int i = 0; i < 4; ++i) {
                ull x2 = pack2(xv_[i], xv_[i]);
                acc[i][0] = ffma2(x2, w0, acc[i][0]);
                acc[i][1] = ffma2(x2, w1, acc[i][1]);
                acc[i][2] = ffma2(x2, w2, acc[i][2]);
                acc[i][3] = ffma2(x2, w3, acc[i][3]);
            }
        }
    }

    __syncthreads();
    // spill raw logits to smem: smem[tok_local][e], stride LS_STRIDE
#pragma unroll
    for (int i = 0; i < 4; ++i) {
        int tl = tg * 4 + i;
#pragma unroll
        for (int j = 0; j < 4; ++j) {
            float lo, hi;
            unpack2(acc[i][j], lo, hi);
            smem[tl * LS_STRIDE + eg * 8 + 2 * j]     = lo;
            smem[tl * LS_STRIDE + eg * 8 + 2 * j + 1] = hi;
        }
    }
    __syncthreads();

    // Epilogue: one token per thread (t < 128)
    if (t < TM) {
        const long tokg = (long)blk * TM + t;
        const float f = 1.0f + 0.1f * sc[sidx_p[0]];   // scalar scale folded into logits
        float* lrow = smem + t * LS_STRIDE;
        const float4* nz = (const float4*)(noise + tokg * NEXP);

        float m = -1e30f;
#pragma unroll
        for (int q = 0; q < 16; ++q) {
            float4 nv = nz[q];
            float n_[4] = {nv.x, nv.y, nv.z, nv.w};
#pragma unroll
            for (int j = 0; j < 4; ++j) {
                float v = f * lrow[q * 4 + j] + 0.1f * n_[j];
                lrow[q * 4 + j] = v;
                m = fmaxf(m, v);
            }
        }

        float sum = 0.0f;
        float p1 = -1.0f, p2 = -1.0f;
        int   i1 = 0,     i2 = 0;
#pragma unroll
        for (int e = 0; e < NEXP; ++e) {
            float p = expf(lrow[e] - m);
            lrow[e] = p;
            sum += p;
            // strict > : lowest index wins ties, matching jax.lax.top_k
            if (p > p1)      { p2 = p1; i2 = i1; p1 = p; i1 = e; }
            else if (p > p2) { p2 = p;  i2 = e; }
        }
        const float inv = 1.0f / sum;
        const float wn  = 1.0f / (p1 + p2);
        const float w1v = p1 * wn, w2v = p2 * wn;

        // dispatch tensor (dense, mostly zero)
        float4* disp = (float4*)out + tokg * 16;
#pragma unroll
        for (int q = 0; q < 16; ++q) {
            float4 z = make_float4(0.f, 0.f, 0.f, 0.f);
            if ((i1 >> 2) == q) (&z.x)[i1 & 3] = w1v;
            if ((i2 >> 2) == q) (&z.x)[i2 & 3] = w2v;
            disp[q] = z;
        }
        if (do_probs) {
            float4* pr = (float4*)(out + (long)NTOK * NEXP) + tokg * 16;
#pragma unroll
            for (int q = 0; q < 16; ++q) {
                float4 z;
                z.x = lrow[q * 4 + 0] * inv;
                z.y = lrow[q * 4 + 1] * inv;
                z.z = lrow[q * 4 + 2] * inv;
                z.w = lrow[q * 4 + 3] * inv;
                pr[q] = z;
            }
        }
        if (do_idx) {
            float* ix = out + 2L * NTOK * NEXP + tokg * 2;
            ix[0] = (float)i1;
            ix[1] = (float)i2;
        }
    }
}

extern "C" void kernel_launch(void* const* d_in, const int* in_sizes, int n_in,
                              void* d_out, int out_size) {
    const float* x     = (const float*)d_in[0];
    const float* W     = (const float*)d_in[1];
    const float* sc    = (const float*)d_in[2];
    const float* noise = (const float*)d_in[3];
    const int*   sidx  = (const int*)d_in[4];
    float* out = (float*)d_out;

    const int do_probs = (out_size >= 2 * NTOK * NEXP) ? 1 : 0;
    const int do_idx   = (out_size >= 2 * NTOK * NEXP + 2 * NTOK) ? 1 : 0;

    router_fused_kernel<<<NTOK / TM, 256>>>(x, W, sc, noise, sidx, out, do_probs, do_idx);
}